// round 10
// baseline (speedup 1.0000x reference)
#include <cuda_runtime.h>
#include <cuda_bf16.h>
#include <cstddef>
#include <cstdint>

#define N_  16
#define K_  256
#define T_  1000
#define M_  384

typedef unsigned long long u64;

// ---------------- scratch (device globals; no allocations) ----------------
__device__ float g_SE[N_ * K_ * 2];          // S, E per (n,k)
__device__ float g_g [N_ * K_ * 16];         // folded layer-1 bias per (n,k)
__device__ float g_ga[N_ * K_ * 2];          // folded aux layer-1 bias
__device__ float g_wc[N_ * 1024 * 2];        // sum_k W*C (before proj)
// W in m16n8k16 A-fragment layout: [n][ttile(64)][ktile(16)][lane(32)] uint4
__device__ uint4 g_Wfh[(size_t)N_ * 64 * 16 * 32];
__device__ uint4 g_Wfl[(size_t)N_ * 64 * 16 * 32];
// V in B-fragment layout: [n][ktile(16)][mtile(48)][lane(32)] uint2
__device__ uint2 g_Vfh[(size_t)N_ * 16 * 48 * 32];
__device__ uint2 g_Vfl[(size_t)N_ * 16 * 48 * 32];

// ---------------- helpers ---------------
__device__ __forceinline__ u64 pk2(float lo, float hi) {
    u64 d; asm("mov.b64 %0, {%1, %2};" : "=l"(d) : "f"(lo), "f"(hi)); return d;
}
__device__ __forceinline__ u64 pkd(float x) {
    u64 d; asm("mov.b64 %0, {%1, %1};" : "=l"(d) : "f"(x)); return d;
}
__device__ __forceinline__ void upk(u64 v, float& lo, float& hi) {
    asm("mov.b64 {%0, %1}, %2;" : "=f"(lo), "=f"(hi) : "l"(v));
}
__device__ __forceinline__ u64 ffma2(u64 a, u64 b, u64 c) {
    u64 d; asm("fma.rn.f32x2 %0, %1, %2, %3;" : "=l"(d) : "l"(a), "l"(b), "l"(c));
    return d;
}
__device__ __forceinline__ float siluf(float x) {
    float th; const float hx = 0.5f * x;
    asm("tanh.approx.f32 %0, %1;" : "=f"(th) : "f"(hx));
    return fmaf(hx, th, hx);
}
__device__ __forceinline__ float ex2f(float x) {
    float r; asm("ex2.approx.f32 %0, %1;" : "=f"(r) : "f"(x)); return r;
}
// pack (even, odd) -> bf16x2 with even in low 16 bits
__device__ __forceinline__ uint32_t pkbf(float even, float odd) {
    uint32_t r; asm("cvt.rn.bf16x2.f32 %0, %1, %2;" : "=r"(r) : "f"(odd), "f"(even));
    return r;
}
__device__ __forceinline__ uint32_t pkbf_res(float even, float odd, uint32_t hp) {
    const float eh = __uint_as_float(hp << 16);
    const float oh = __uint_as_float(hp & 0xFFFF0000u);
    return pkbf(even - eh, odd - oh);
}
__device__ __forceinline__ void mma_bf16(float d[4], const uint4& a, const uint2& b) {
    asm("mma.sync.aligned.m16n8k16.row.col.f32.bf16.bf16.f32 "
        "{%0,%1,%2,%3},{%4,%5,%6,%7},{%8,%9},{%0,%1,%2,%3};"
        : "+f"(d[0]), "+f"(d[1]), "+f"(d[2]), "+f"(d[3])
        : "r"(a.x), "r"(a.y), "r"(a.z), "r"(a.w), "r"(b.x), "r"(b.y));
}

// ---------------------------------------------------------------------------
// Kernel 0: durations + scan -> S,E.
// ---------------------------------------------------------------------------
__global__ void scan_kernel(const float* __restrict__ dur_out)
{
    __shared__ float wsum[8];
    const int n = blockIdx.x, k = threadIdx.x;
    const int lane = k & 31, warp = k >> 5;

    const float d = fmaxf(__expf(dur_out[n * K_ + k]) - 1.0f, 0.0f);
    float x = d;
#pragma unroll
    for (int off = 1; off < 32; off <<= 1) {
        float y = __shfl_up_sync(0xFFFFFFFFu, x, off);
        if (lane >= off) x += y;
    }
    if (lane == 31) wsum[warp] = x;
    __syncthreads();
    float off = 0.0f;
#pragma unroll
    for (int w = 0; w < 8; w++) off += (w < warp) ? wsum[w] : 0.0f;
    const float Ev = x + off, Sv = Ev - d;
    g_SE[(n * K_ + k) * 2 + 0] = Sv;
    g_SE[(n * K_ + k) * 2 + 1] = Ev;
}

// ---------------------------------------------------------------------------
// Kernel 1: Conv1D(3,same)+BN+silu, fold into g/ga. One warp per (n,k).
// ---------------------------------------------------------------------------
__global__ __launch_bounds__(256) void conv_fold_kernel(
    const float* __restrict__ V,
    const float* __restrict__ conv_w,
    const float* __restrict__ conv_b,
    const float* __restrict__ bn_gamma, const float* __restrict__ bn_beta,
    const float* __restrict__ bn_mean,  const float* __restrict__ bn_var,
    const float* __restrict__ w1,
    const float* __restrict__ b1,
    const float* __restrict__ aw1,
    const float* __restrict__ ab1)
{
    const int tid  = threadIdx.x;
    const int lane = tid & 31;
    const int widx = blockIdx.x * 8 + (tid >> 5);
    const int n = widx >> 8, k = widx & 255;

    u64 acc2[4] = {0ull, 0ull, 0ull, 0ull};
#pragma unroll
    for (int tap = 0; tap < 3; tap++) {
        const int kk = k - 1 + tap;
        if (kk < 0 || kk >= K_) continue;
        const float* vrow = V + ((size_t)n * K_ + kk) * M_;
#pragma unroll
        for (int i = 0; i < 3; i++) {
            const int c0 = i * 128 + lane * 4;
            const float4 v = *reinterpret_cast<const float4*>(vrow + c0);
            const float vv[4] = { v.x, v.y, v.z, v.w };
#pragma unroll
            for (int cc = 0; cc < 4; cc++) {
                const u64 vd = pkd(vv[cc]);
                const float4* wp = reinterpret_cast<const float4*>(
                    conv_w + ((size_t)tap * M_ + c0 + cc) * 8);
                const float4 wa = wp[0], wb = wp[1];
                acc2[0] = ffma2(vd, pk2(wa.x, wa.y), acc2[0]);
                acc2[1] = ffma2(vd, pk2(wa.z, wa.w), acc2[1]);
                acc2[2] = ffma2(vd, pk2(wb.x, wb.y), acc2[2]);
                acc2[3] = ffma2(vd, pk2(wb.z, wb.w), acc2[3]);
            }
        }
    }
    float acc[8];
#pragma unroll
    for (int j = 0; j < 4; j++) upk(acc2[j], acc[2 * j], acc[2 * j + 1]);
#pragma unroll
    for (int s = 16; s > 0; s >>= 1)
#pragma unroll
        for (int o = 0; o < 8; o++)
            acc[o] += __shfl_xor_sync(0xFFFFFFFFu, acc[o], s);

    float cv[8];
#pragma unroll
    for (int o = 0; o < 8; o++) {
        float y = (acc[o] + conv_b[o] - bn_mean[o]) * rsqrtf(bn_var[o] + 1e-3f)
                  * bn_gamma[o] + bn_beta[o];
        cv[o] = siluf(y);
    }
    const float Sv = g_SE[(n * K_ + k) * 2 + 0];
    const float Ev = g_SE[(n * K_ + k) * 2 + 1];
    if (lane < 16) {
        const int j = lane;
        float gj = b1[j] - Sv * w1[j] + Ev * w1[16 + j];
#pragma unroll
        for (int c = 0; c < 8; c++) gj = fmaf(cv[c], w1[(2 + c) * 16 + j], gj);
        g_g[((size_t)n * K_ + k) * 16 + j] = gj;
    } else if (lane < 18) {
        const int p = lane - 16;
        float gp = ab1[p] - Sv * aw1[p] + Ev * aw1[2 + p];
#pragma unroll
        for (int c = 0; c < 8; c++) gp = fmaf(cv[c], aw1[(2 + c) * 2 + p], gp);
        g_ga[((size_t)n * K_ + k) * 2 + p] = gp;
    }
}

// ---------------------------------------------------------------------------
// Kernel V: convert V into bf16 hi/lo B-fragment layout.
// Grid (16 ktile, 16 n), block 256.
// ---------------------------------------------------------------------------
__global__ __launch_bounds__(256) void vconv_kernel(const float* __restrict__ V)
{
    __shared__ float sV[16][388];
    const int kt = blockIdx.x, n = blockIdx.y;
    const int tid = threadIdx.x;

    const float* src = V + ((size_t)n * K_ + kt * 16) * M_;
#pragma unroll
    for (int it = 0; it < 6; it++) {
        const int idx = it * 256 + tid;
        const int row = idx / 96, c4 = idx % 96;
        const float4 v = reinterpret_cast<const float4*>(src + (size_t)row * M_)[c4];
        *reinterpret_cast<float4*>(&sV[row][c4 * 4]) = v;
    }
    __syncthreads();

#pragma unroll
    for (int it = 0; it < 6; it++) {
        const int s = it * 256 + tid;
        const int mt = s >> 5, cl = s & 31;
        const int g2 = cl >> 2, tg = cl & 3;
        const int m = mt * 8 + g2, k0 = 2 * tg;
        const float v00 = sV[k0][m],     v01 = sV[k0 + 1][m];
        const float v10 = sV[k0 + 8][m], v11 = sV[k0 + 9][m];
        uint2 H, L;
        H.x = pkbf(v00, v01); H.y = pkbf(v10, v11);
        L.x = pkbf_res(v00, v01, H.x); L.y = pkbf_res(v10, v11, H.y);
        const size_t fi = (((size_t)n * 16 + kt) * 48 + mt) * 32 + cl;
        g_Vfh[fi] = H; g_Vfl[fi] = L;
    }
}

// ---------------------------------------------------------------------------
// Kernel 2: score MLP + softmax + aux. Thread-per-k, 16-t tile per block.
// g[16] resident; per-t loops NOT unrolled (caps live registers);
// __launch_bounds__(256,2) forces <=128 regs -> 2 CTAs/SM.
// Grid (64 ttile, 16 n), block 256. Writes W as bf16 hi/lo A-fragments + g_wc.
// ---------------------------------------------------------------------------
__global__ __launch_bounds__(256, 2) void score_kernel(
    const float* __restrict__ w1,
    const float* __restrict__ w2,
    const float* __restrict__ b2,
    const float* __restrict__ w3,
    const float* __restrict__ b3,
    const float* __restrict__ aw1,
    const float* __restrict__ aw2,
    const float* __restrict__ ab2)
{
    __shared__ __align__(16) u64 s_w2[16][8];
    __shared__ float s_d1[16], s_b2[16], s_w3[16];
    __shared__ float sW[16][257];
    __shared__ float smax[16][8];
    __shared__ float spart[16][8][3];
    __shared__ float sinv[16];

    const int k    = threadIdx.x;      // 0..255
    const int lane = k & 31, warp = k >> 5;
    const int tt   = blockIdx.x;       // ttile 0..63
    const int n    = blockIdx.y;
    const float tb = (float)(tt * 16 + 1);

    if (k < 128) {
        const int i = k & 15, j2 = k >> 4;
        s_w2[i][j2] = pk2(w2[(2 * j2) * 16 + i], w2[(2 * j2 + 1) * 16 + i]);
    }
    if (k < 16) { s_d1[k] = w1[k] - w1[16 + k]; s_b2[k] = b2[k]; s_w3[k] = w3[k]; }
    __syncthreads();

    // per-thread folded biases (resident for all 16 t)
    float g[16];
    {
        const float4* gp = reinterpret_cast<const float4*>(
            g_g + ((size_t)n * K_ + k) * 16);
#pragma unroll
        for (int q = 0; q < 4; q++) {
            const float4 v = gp[q];
            g[4 * q] = v.x; g[4 * q + 1] = v.y; g[4 * q + 2] = v.z; g[4 * q + 3] = v.w;
        }
    }
    const float2 gaq = *reinterpret_cast<const float2*>(g_ga + ((size_t)n * K_ + k) * 2);
    const float b3v = b3[0];
    const float da0 = aw1[0] - aw1[2], da1 = aw1[1] - aw1[3];
    const float aw20 = aw2[0], aw21 = aw2[1], aw22 = aw2[2], aw23 = aw2[3];
    const float ab20 = ab2[0], ab21 = ab2[1];

    // ---- phase 1: raw scores -> shared; warp-max partials (NOT unrolled) ----
#pragma unroll 1
    for (int tloc = 0; tloc < 16; tloc++) {
        const float t = tb + (float)tloc;
        u64 h2[8];
#pragma unroll
        for (int j2 = 0; j2 < 8; j2++) {
            const float a = siluf(fmaf(t, s_d1[2 * j2],     g[2 * j2]));
            const float b = siluf(fmaf(t, s_d1[2 * j2 + 1], g[2 * j2 + 1]));
            h2[j2] = pk2(a, b);
        }
        float sc = b3v;
#pragma unroll
        for (int i = 0; i < 16; i++) {
            u64 acc = pk2(s_b2[i], 0.0f);
            const u64* wr = s_w2[i];
#pragma unroll
            for (int j2 = 0; j2 < 8; j2++) acc = ffma2(h2[j2], wr[j2], acc);
            float lo, hi; upk(acc, lo, hi);
            sc = fmaf(siluf(lo + hi), s_w3[i], sc);
        }
        sW[tloc][k] = sc;

        float m = sc;
#pragma unroll
        for (int s = 16; s > 0; s >>= 1)
            m = fmaxf(m, __shfl_xor_sync(0xFFFFFFFFu, m, s));
        if (lane == 0) smax[tloc][warp] = m;
    }
    __syncthreads();

    // ---- phase 2: exp + aux recompute + warp-sum partials (NOT unrolled) ----
    const float L2E = 1.4426950408889634f;
#pragma unroll 1
    for (int tloc = 0; tloc < 16; tloc++) {
        const float t = tb + (float)tloc;
        float mx = smax[tloc][0];
#pragma unroll
        for (int w = 1; w < 8; w++) mx = fmaxf(mx, smax[tloc][w]);
        const float ev = ex2f((sW[tloc][k] - mx) * L2E);

        const float a0 = siluf(fmaf(t, da0, gaq.x));
        const float a1 = siluf(fmaf(t, da1, gaq.y));
        const float c20 = siluf(ab20 + a0 * aw20 + a1 * aw22);
        const float c21 = siluf(ab21 + a0 * aw21 + a1 * aw23);

        float s0 = ev, s1 = ev * c20, s2 = ev * c21;
#pragma unroll
        for (int s = 16; s > 0; s >>= 1) {
            s0 += __shfl_xor_sync(0xFFFFFFFFu, s0, s);
            s1 += __shfl_xor_sync(0xFFFFFFFFu, s1, s);
            s2 += __shfl_xor_sync(0xFFFFFFFFu, s2, s);
        }
        if (lane == 0) {
            spart[tloc][warp][0] = s0;
            spart[tloc][warp][1] = s1;
            spart[tloc][warp][2] = s2;
        }
        sW[tloc][k] = ev;
    }
    __syncthreads();

    // ---- totals: one thread per t ----
    if (k < 16) {
        float t0s = 0.0f, t1s = 0.0f, t2s = 0.0f;
#pragma unroll
        for (int w = 0; w < 8; w++) {
            t0s += spart[k][w][0]; t1s += spart[k][w][1]; t2s += spart[k][w][2];
        }
        const float inv = __fdividef(1.0f, t0s);
        sinv[k] = inv;
        *reinterpret_cast<float2*>(&g_wc[((size_t)n * 1024 + tt * 16 + k) * 2]) =
            make_float2(t1s * inv, t2s * inv);
    }
    __syncthreads();

    // ---- phase 3: normalize in shared ----
#pragma unroll 1
    for (int tloc = 0; tloc < 16; tloc++)
        sW[tloc][k] *= sinv[tloc];
    __syncthreads();

    // ---- fragment conversion (bf16 hi/lo, coalesced STG.128) ----
#pragma unroll 1
    for (int it2 = 0; it2 < 2; it2++) {
        const int idx = it2 * 256 + k;
        const int kt = idx >> 5, cl = idx & 31;
        const int g2 = cl >> 2, tg = cl & 3;
        const int c0 = kt * 16 + 2 * tg;
        const float e00 = sW[g2][c0],         e01 = sW[g2][c0 + 1];
        const float e10 = sW[g2 + 8][c0],     e11 = sW[g2 + 8][c0 + 1];
        const float e20 = sW[g2][c0 + 8],     e21 = sW[g2][c0 + 9];
        const float e30 = sW[g2 + 8][c0 + 8], e31 = sW[g2 + 8][c0 + 9];
        uint4 H, L;
        H.x = pkbf(e00, e01); H.y = pkbf(e10, e11);
        H.z = pkbf(e20, e21); H.w = pkbf(e30, e31);
        L.x = pkbf_res(e00, e01, H.x); L.y = pkbf_res(e10, e11, H.y);
        L.z = pkbf_res(e20, e21, H.z); L.w = pkbf_res(e30, e31, H.w);
        const size_t fi = (((size_t)n * 64 + tt) * 16 + kt) * 32 + cl;
        g_Wfh[fi] = H; g_Wfl[fi] = L;
    }
}

// ---------------------------------------------------------------------------
// Kernel 3: O = W @ V + wc @ proj_w via bf16-split mma.sync, no smem.
// Grid (3, 8, 16), block 512 (16 warps, 4x4). Warp tile 32(t) x 32(m).
// ---------------------------------------------------------------------------
__global__ __launch_bounds__(512) void out_gemm_kernel(
    const float* __restrict__ proj_w,  // [2,M]
    float* __restrict__ O)             // [N,T,M]
{
    const int n  = blockIdx.z;
    const int tid = threadIdx.x;
    const int l   = tid & 31;
    const int wi  = tid >> 5;
    const int wm  = wi >> 2, wn = wi & 3;

    const int tt0 = blockIdx.y * 8 + wm * 2;       // ttile base (16-row units)
    const int mt0 = blockIdx.x * 16 + wn * 4;      // mtile base (8-col units)

    const uint4* WH = g_Wfh; const uint4* WL = g_Wfl;
    const uint2* VH = g_Vfh; const uint2* VL = g_Vfl;

    float D[2][4][4];
#pragma unroll
    for (int i = 0; i < 2; i++)
#pragma unroll
        for (int j = 0; j < 4; j++)
#pragma unroll
            for (int q = 0; q < 4; q++) D[i][j][q] = 0.0f;

    uint4 Ah[2][2], Al[2][2];
    uint2 Bh[2][4], Bl[2][4];

#define LOADK(KT, B) do {                                                     \
        const size_t a0i = (((size_t)n * 64 + tt0) * 16 + (KT)) * 32 + l;     \
        const size_t a1i = a0i + 16 * 32;                                     \
        Ah[B][0] = WH[a0i]; Ah[B][1] = WH[a1i];                               \
        Al[B][0] = WL[a0i]; Al[B][1] = WL[a1i];                               \
        const size_t bbi = (((size_t)n * 16 + (KT)) * 48 + mt0) * 32 + l;     \
        _Pragma("unroll")                                                     \
        for (int j = 0; j < 4; j++) {                                         \
            Bh[B][j] = VH[bbi + (size_t)j * 32];                              \
            Bl[B][j] = VL[bbi + (size_t)j * 32];                              \
        }                                                                     \
    } while (0)

    LOADK(0, 0);
#pragma unroll
    for (int kt = 0; kt < 16; kt++) {
        const int cb = kt & 1;
        if (kt < 15) LOADK(kt + 1, cb ^ 1);
#pragma unroll
        for (int i = 0; i < 2; i++)
#pragma unroll
            for (int j = 0; j < 4; j++) {
                mma_bf16(D[i][j], Ah[cb][i], Bh[cb][j]);
                mma_bf16(D[i][j], Ah[cb][i], Bl[cb][j]);
                mma_bf16(D[i][j], Al[cb][i], Bh[cb][j]);
            }
    }
#undef LOADK

    // epilogue
    const int g2 = l >> 2, tg = l & 3;
    float2 pj0[4], pj1[4];
#pragma unroll
    for (int j = 0; j < 4; j++) {
        const int m = (mt0 + j) * 8 + 2 * tg;
        pj0[j] = *reinterpret_cast<const float2*>(&proj_w[m]);
        pj1[j] = *reinterpret_cast<const float2*>(&proj_w[M_ + m]);
    }
#pragma unroll
    for (int i = 0; i < 2; i++) {
        const int r0 = (tt0 + i) * 16 + g2;
        const int r1 = r0 + 8;
        float2 wcA = make_float2(0.f, 0.f), wcB = wcA;
        if (r0 < T_) wcA = *reinterpret_cast<const float2*>(&g_wc[((size_t)n * 1024 + r0) * 2]);
        if (r1 < T_) wcB = *reinterpret_cast<const float2*>(&g_wc[((size_t)n * 1024 + r1) * 2]);
#pragma unroll
        for (int j = 0; j < 4; j++) {
            const int m = (mt0 + j) * 8 + 2 * tg;
            if (r0 < T_) {
                float2 o;
                o.x = D[i][j][0] + wcA.x * pj0[j].x + wcA.y * pj1[j].x;
                o.y = D[i][j][1] + wcA.x * pj0[j].y + wcA.y * pj1[j].y;
                *reinterpret_cast<float2*>(&O[((size_t)n * T_ + r0) * M_ + m]) = o;
            }
            if (r1 < T_) {
                float2 o;
                o.x = D[i][j][2] + wcB.x * pj0[j].x + wcB.y * pj1[j].x;
                o.y = D[i][j][3] + wcB.x * pj0[j].y + wcB.y * pj1[j].y;
                *reinterpret_cast<float2*>(&O[((size_t)n * T_ + r1) * M_ + m]) = o;
            }
        }
    }
}

// ---------------------------------------------------------------------------
extern "C" void kernel_launch(void* const* d_in, const int* in_sizes, int n_in,
                              void* d_out, int out_size)
{
    const float* V        = (const float*)d_in[0];
    const float* dur      = (const float*)d_in[1];
    const float* conv_w   = (const float*)d_in[2];
    const float* conv_b   = (const float*)d_in[3];
    const float* bn_gamma = (const float*)d_in[4];
    const float* bn_beta  = (const float*)d_in[5];
    const float* bn_mean  = (const float*)d_in[6];
    const float* bn_var   = (const float*)d_in[7];
    const float* w1       = (const float*)d_in[8];
    const float* b1       = (const float*)d_in[9];
    const float* w2       = (const float*)d_in[10];
    const float* b2       = (const float*)d_in[11];
    const float* w3       = (const float*)d_in[12];
    const float* b3       = (const float*)d_in[13];
    const float* aw1      = (const float*)d_in[14];
    const float* ab1      = (const float*)d_in[15];
    const float* aw2      = (const float*)d_in[16];
    const float* ab2      = (const float*)d_in[17];
    const float* proj_w   = (const float*)d_in[18];
    float* O = (float*)d_out;

    scan_kernel<<<N_, K_>>>(dur);
    vconv_kernel<<<dim3(16, N_), 256>>>(V);
    conv_fold_kernel<<<(N_ * K_) / 8, 256>>>(V, conv_w, conv_b, bn_gamma, bn_beta,
                                             bn_mean, bn_var, w1, b1, aw1, ab1);
    score_kernel<<<dim3(64, N_), 256>>>(w1, w2, b2, w3, b3, aw1, aw2, ab2);
    out_gemm_kernel<<<dim3(3, 8, N_), 512>>>(proj_w, O);
}

// round 11
// speedup vs baseline: 1.9593x; 1.9593x over previous
#include <cuda_runtime.h>
#include <cuda_bf16.h>
#include <cstddef>
#include <cstdint>

#define N_  16
#define K_  256
#define T_  1000
#define M_  384

typedef unsigned long long u64;

// ---------------- scratch (device globals; no allocations) ----------------
__device__ float g_SE[N_ * K_ * 2];          // S, E per (n,k)
__device__ float g_g [N_ * K_ * 16];         // folded layer-1 bias per (n,k)
__device__ float g_ga[N_ * K_ * 2];          // folded aux layer-1 bias
__device__ float g_wc[N_ * 1024 * 2];        // sum_k W*C (before proj)
// W in m16n8k16 A-fragment layout: [n][ttile(64)][ktile(16)][lane(32)] uint4
__device__ uint4 g_Wfh[(size_t)N_ * 64 * 16 * 32];
__device__ uint4 g_Wfl[(size_t)N_ * 64 * 16 * 32];
// V in B-fragment layout: [n][ktile(16)][mtile(48)][lane(32)] uint2
__device__ uint2 g_Vfh[(size_t)N_ * 16 * 48 * 32];
__device__ uint2 g_Vfl[(size_t)N_ * 16 * 48 * 32];

// ---------------- helpers ---------------
__device__ __forceinline__ u64 pk2(float lo, float hi) {
    u64 d; asm("mov.b64 %0, {%1, %2};" : "=l"(d) : "f"(lo), "f"(hi)); return d;
}
__device__ __forceinline__ u64 pkd(float x) {
    u64 d; asm("mov.b64 %0, {%1, %1};" : "=l"(d) : "f"(x)); return d;
}
__device__ __forceinline__ void upk(u64 v, float& lo, float& hi) {
    asm("mov.b64 {%0, %1}, %2;" : "=f"(lo), "=f"(hi) : "l"(v));
}
__device__ __forceinline__ u64 ffma2(u64 a, u64 b, u64 c) {
    u64 d; asm("fma.rn.f32x2 %0, %1, %2, %3;" : "=l"(d) : "l"(a), "l"(b), "l"(c));
    return d;
}
__device__ __forceinline__ float siluf(float x) {
    float th; const float hx = 0.5f * x;
    asm("tanh.approx.f32 %0, %1;" : "=f"(th) : "f"(hx));
    return fmaf(hx, th, hx);
}
__device__ __forceinline__ float ex2f(float x) {
    float r; asm("ex2.approx.f32 %0, %1;" : "=f"(r) : "f"(x)); return r;
}
// pack (even, odd) -> bf16x2 with even in low 16 bits
__device__ __forceinline__ uint32_t pkbf(float even, float odd) {
    uint32_t r; asm("cvt.rn.bf16x2.f32 %0, %1, %2;" : "=r"(r) : "f"(odd), "f"(even));
    return r;
}
__device__ __forceinline__ uint32_t pkbf_res(float even, float odd, uint32_t hp) {
    const float eh = __uint_as_float(hp << 16);
    const float oh = __uint_as_float(hp & 0xFFFF0000u);
    return pkbf(even - eh, odd - oh);
}
__device__ __forceinline__ void mma_bf16(float d[4], const uint4& a, const uint2& b) {
    asm("mma.sync.aligned.m16n8k16.row.col.f32.bf16.bf16.f32 "
        "{%0,%1,%2,%3},{%4,%5,%6,%7},{%8,%9},{%0,%1,%2,%3};"
        : "+f"(d[0]), "+f"(d[1]), "+f"(d[2]), "+f"(d[3])
        : "r"(a.x), "r"(a.y), "r"(a.z), "r"(a.w), "r"(b.x), "r"(b.y));
}

// ---------------------------------------------------------------------------
// Kernel 0: durations + scan -> S,E.
// ---------------------------------------------------------------------------
__global__ void scan_kernel(const float* __restrict__ dur_out)
{
    __shared__ float wsum[8];
    const int n = blockIdx.x, k = threadIdx.x;
    const int lane = k & 31, warp = k >> 5;

    const float d = fmaxf(__expf(dur_out[n * K_ + k]) - 1.0f, 0.0f);
    float x = d;
#pragma unroll
    for (int off = 1; off < 32; off <<= 1) {
        float y = __shfl_up_sync(0xFFFFFFFFu, x, off);
        if (lane >= off) x += y;
    }
    if (lane == 31) wsum[warp] = x;
    __syncthreads();
    float off = 0.0f;
#pragma unroll
    for (int w = 0; w < 8; w++) off += (w < warp) ? wsum[w] : 0.0f;
    const float Ev = x + off, Sv = Ev - d;
    g_SE[(n * K_ + k) * 2 + 0] = Sv;
    g_SE[(n * K_ + k) * 2 + 1] = Ev;
}

// ---------------------------------------------------------------------------
// Kernel 1: Conv1D(3,same)+BN+silu, fold into g/ga. One warp per (n,k).
// ---------------------------------------------------------------------------
__global__ __launch_bounds__(256) void conv_fold_kernel(
    const float* __restrict__ V,
    const float* __restrict__ conv_w,
    const float* __restrict__ conv_b,
    const float* __restrict__ bn_gamma, const float* __restrict__ bn_beta,
    const float* __restrict__ bn_mean,  const float* __restrict__ bn_var,
    const float* __restrict__ w1,
    const float* __restrict__ b1,
    const float* __restrict__ aw1,
    const float* __restrict__ ab1)
{
    const int tid  = threadIdx.x;
    const int lane = tid & 31;
    const int widx = blockIdx.x * 8 + (tid >> 5);
    const int n = widx >> 8, k = widx & 255;

    u64 acc2[4] = {0ull, 0ull, 0ull, 0ull};
#pragma unroll
    for (int tap = 0; tap < 3; tap++) {
        const int kk = k - 1 + tap;
        if (kk < 0 || kk >= K_) continue;
        const float* vrow = V + ((size_t)n * K_ + kk) * M_;
#pragma unroll
        for (int i = 0; i < 3; i++) {
            const int c0 = i * 128 + lane * 4;
            const float4 v = *reinterpret_cast<const float4*>(vrow + c0);
            const float vv[4] = { v.x, v.y, v.z, v.w };
#pragma unroll
            for (int cc = 0; cc < 4; cc++) {
                const u64 vd = pkd(vv[cc]);
                const float4* wp = reinterpret_cast<const float4*>(
                    conv_w + ((size_t)tap * M_ + c0 + cc) * 8);
                const float4 wa = wp[0], wb = wp[1];
                acc2[0] = ffma2(vd, pk2(wa.x, wa.y), acc2[0]);
                acc2[1] = ffma2(vd, pk2(wa.z, wa.w), acc2[1]);
                acc2[2] = ffma2(vd, pk2(wb.x, wb.y), acc2[2]);
                acc2[3] = ffma2(vd, pk2(wb.z, wb.w), acc2[3]);
            }
        }
    }
    float acc[8];
#pragma unroll
    for (int j = 0; j < 4; j++) upk(acc2[j], acc[2 * j], acc[2 * j + 1]);
#pragma unroll
    for (int s = 16; s > 0; s >>= 1)
#pragma unroll
        for (int o = 0; o < 8; o++)
            acc[o] += __shfl_xor_sync(0xFFFFFFFFu, acc[o], s);

    float cv[8];
#pragma unroll
    for (int o = 0; o < 8; o++) {
        float y = (acc[o] + conv_b[o] - bn_mean[o]) * rsqrtf(bn_var[o] + 1e-3f)
                  * bn_gamma[o] + bn_beta[o];
        cv[o] = siluf(y);
    }
    const float Sv = g_SE[(n * K_ + k) * 2 + 0];
    const float Ev = g_SE[(n * K_ + k) * 2 + 1];
    if (lane < 16) {
        const int j = lane;
        float gj = b1[j] - Sv * w1[j] + Ev * w1[16 + j];
#pragma unroll
        for (int c = 0; c < 8; c++) gj = fmaf(cv[c], w1[(2 + c) * 16 + j], gj);
        g_g[((size_t)n * K_ + k) * 16 + j] = gj;
    } else if (lane < 18) {
        const int p = lane - 16;
        float gp = ab1[p] - Sv * aw1[p] + Ev * aw1[2 + p];
#pragma unroll
        for (int c = 0; c < 8; c++) gp = fmaf(cv[c], aw1[(2 + c) * 2 + p], gp);
        g_ga[((size_t)n * K_ + k) * 2 + p] = gp;
    }
}

// ---------------------------------------------------------------------------
// Kernel V: convert V into bf16 hi/lo B-fragment layout.
// Grid (16 ktile, 16 n), block 256.
// ---------------------------------------------------------------------------
__global__ __launch_bounds__(256) void vconv_kernel(const float* __restrict__ V)
{
    __shared__ float sV[16][388];
    const int kt = blockIdx.x, n = blockIdx.y;
    const int tid = threadIdx.x;

    const float* src = V + ((size_t)n * K_ + kt * 16) * M_;
#pragma unroll
    for (int it = 0; it < 6; it++) {
        const int idx = it * 256 + tid;
        const int row = idx / 96, c4 = idx % 96;
        const float4 v = reinterpret_cast<const float4*>(src + (size_t)row * M_)[c4];
        *reinterpret_cast<float4*>(&sV[row][c4 * 4]) = v;
    }
    __syncthreads();

#pragma unroll
    for (int it = 0; it < 6; it++) {
        const int s = it * 256 + tid;
        const int mt = s >> 5, cl = s & 31;
        const int g2 = cl >> 2, tg = cl & 3;
        const int m = mt * 8 + g2, k0 = 2 * tg;
        const float v00 = sV[k0][m],     v01 = sV[k0 + 1][m];
        const float v10 = sV[k0 + 8][m], v11 = sV[k0 + 9][m];
        uint2 H, L;
        H.x = pkbf(v00, v01); H.y = pkbf(v10, v11);
        L.x = pkbf_res(v00, v01, H.x); L.y = pkbf_res(v10, v11, H.y);
        const size_t fi = (((size_t)n * 16 + kt) * 48 + mt) * 32 + cl;
        g_Vfh[fi] = H; g_Vfl[fi] = L;
    }
}

// ---------------------------------------------------------------------------
// Kernel 2: score MLP + softmax + aux. Thread-per-k, 16-t tile per block.
// tloc loops unrolled x2 (cross-t ILP + w2 LDS reuse); layer-2 i-loop split
// into 8x2 with two accumulators so only ~16 u64 of w2 are live at once
// (prevents the 128-LDS hoist that spilled in earlier rounds).
// Grid (64 ttile, 16 n), block 256. Writes W as bf16 hi/lo A-fragments + g_wc.
// ---------------------------------------------------------------------------
__global__ __launch_bounds__(256, 2) void score_kernel(
    const float* __restrict__ w1,
    const float* __restrict__ w2,
    const float* __restrict__ b2,
    const float* __restrict__ w3,
    const float* __restrict__ b3,
    const float* __restrict__ aw1,
    const float* __restrict__ aw2,
    const float* __restrict__ ab2)
{
    __shared__ __align__(16) u64 s_w2[16][8];
    __shared__ float s_d1[16], s_b2[16], s_w3[16];
    __shared__ float sW[16][257];
    __shared__ float smax[16][8];
    __shared__ float spart[16][8][3];
    __shared__ float sinv[16];

    const int k    = threadIdx.x;      // 0..255
    const int lane = k & 31, warp = k >> 5;
    const int tt   = blockIdx.x;       // ttile 0..63
    const int n    = blockIdx.y;
    const float tb = (float)(tt * 16 + 1);

    if (k < 128) {
        const int i = k & 15, j2 = k >> 4;
        s_w2[i][j2] = pk2(w2[(2 * j2) * 16 + i], w2[(2 * j2 + 1) * 16 + i]);
    }
    if (k < 16) { s_d1[k] = w1[k] - w1[16 + k]; s_b2[k] = b2[k]; s_w3[k] = w3[k]; }
    __syncthreads();

    // per-thread folded biases (resident for all 16 t)
    float g[16];
    {
        const float4* gp = reinterpret_cast<const float4*>(
            g_g + ((size_t)n * K_ + k) * 16);
#pragma unroll
        for (int q = 0; q < 4; q++) {
            const float4 v = gp[q];
            g[4 * q] = v.x; g[4 * q + 1] = v.y; g[4 * q + 2] = v.z; g[4 * q + 3] = v.w;
        }
    }
    const float2 gaq = *reinterpret_cast<const float2*>(g_ga + ((size_t)n * K_ + k) * 2);
    const float b3v = b3[0];
    const float da0 = aw1[0] - aw1[2], da1 = aw1[1] - aw1[3];
    const float aw20 = aw2[0], aw21 = aw2[1], aw22 = aw2[2], aw23 = aw2[3];
    const float ab20 = ab2[0], ab21 = ab2[1];

    // ---- phase 1: raw scores -> shared; warp-max partials ----
#pragma unroll 2
    for (int tloc = 0; tloc < 16; tloc++) {
        const float t = tb + (float)tloc;
        u64 h2[8];
#pragma unroll
        for (int j2 = 0; j2 < 8; j2++) {
            const float a = siluf(fmaf(t, s_d1[2 * j2],     g[2 * j2]));
            const float b = siluf(fmaf(t, s_d1[2 * j2 + 1], g[2 * j2 + 1]));
            h2[j2] = pk2(a, b);
        }
        float sc0 = 0.0f, sc1 = 0.0f;
#pragma unroll 2
        for (int ii = 0; ii < 8; ii++) {
            const int i0 = 2 * ii, i1 = 2 * ii + 1;
            u64 acc0 = pk2(s_b2[i0], 0.0f);
            u64 acc1 = pk2(s_b2[i1], 0.0f);
            const u64* wr0 = s_w2[i0];
            const u64* wr1 = s_w2[i1];
#pragma unroll
            for (int j2 = 0; j2 < 8; j2++) {
                acc0 = ffma2(h2[j2], wr0[j2], acc0);
                acc1 = ffma2(h2[j2], wr1[j2], acc1);
            }
            float lo0, hi0, lo1, hi1;
            upk(acc0, lo0, hi0);
            upk(acc1, lo1, hi1);
            sc0 = fmaf(siluf(lo0 + hi0), s_w3[i0], sc0);
            sc1 = fmaf(siluf(lo1 + hi1), s_w3[i1], sc1);
        }
        const float sc = b3v + sc0 + sc1;
        sW[tloc][k] = sc;

        float m = sc;
#pragma unroll
        for (int s = 16; s > 0; s >>= 1)
            m = fmaxf(m, __shfl_xor_sync(0xFFFFFFFFu, m, s));
        if (lane == 0) smax[tloc][warp] = m;
    }
    __syncthreads();

    // ---- phase 2: exp + aux recompute + warp-sum partials ----
    const float L2E = 1.4426950408889634f;
#pragma unroll 2
    for (int tloc = 0; tloc < 16; tloc++) {
        const float t = tb + (float)tloc;
        float mx = smax[tloc][0];
#pragma unroll
        for (int w = 1; w < 8; w++) mx = fmaxf(mx, smax[tloc][w]);
        const float ev = ex2f((sW[tloc][k] - mx) * L2E);

        const float a0 = siluf(fmaf(t, da0, gaq.x));
        const float a1 = siluf(fmaf(t, da1, gaq.y));
        const float c20 = siluf(ab20 + a0 * aw20 + a1 * aw22);
        const float c21 = siluf(ab21 + a0 * aw21 + a1 * aw23);

        float s0 = ev, s1 = ev * c20, s2 = ev * c21;
#pragma unroll
        for (int s = 16; s > 0; s >>= 1) {
            s0 += __shfl_xor_sync(0xFFFFFFFFu, s0, s);
            s1 += __shfl_xor_sync(0xFFFFFFFFu, s1, s);
            s2 += __shfl_xor_sync(0xFFFFFFFFu, s2, s);
        }
        if (lane == 0) {
            spart[tloc][warp][0] = s0;
            spart[tloc][warp][1] = s1;
            spart[tloc][warp][2] = s2;
        }
        sW[tloc][k] = ev;
    }
    __syncthreads();

    // ---- totals: one thread per t ----
    if (k < 16) {
        float t0s = 0.0f, t1s = 0.0f, t2s = 0.0f;
#pragma unroll
        for (int w = 0; w < 8; w++) {
            t0s += spart[k][w][0]; t1s += spart[k][w][1]; t2s += spart[k][w][2];
        }
        const float inv = __fdividef(1.0f, t0s);
        sinv[k] = inv;
        *reinterpret_cast<float2*>(&g_wc[((size_t)n * 1024 + tt * 16 + k) * 2]) =
            make_float2(t1s * inv, t2s * inv);
    }
    __syncthreads();

    // ---- phase 3: normalize in shared ----
#pragma unroll 2
    for (int tloc = 0; tloc < 16; tloc++)
        sW[tloc][k] *= sinv[tloc];
    __syncthreads();

    // ---- fragment conversion (bf16 hi/lo, coalesced STG.128) ----
#pragma unroll 1
    for (int it2 = 0; it2 < 2; it2++) {
        const int idx = it2 * 256 + k;
        const int kt = idx >> 5, cl = idx & 31;
        const int g2 = cl >> 2, tg = cl & 3;
        const int c0 = kt * 16 + 2 * tg;
        const float e00 = sW[g2][c0],         e01 = sW[g2][c0 + 1];
        const float e10 = sW[g2 + 8][c0],     e11 = sW[g2 + 8][c0 + 1];
        const float e20 = sW[g2][c0 + 8],     e21 = sW[g2][c0 + 9];
        const float e30 = sW[g2 + 8][c0 + 8], e31 = sW[g2 + 8][c0 + 9];
        uint4 H, L;
        H.x = pkbf(e00, e01); H.y = pkbf(e10, e11);
        H.z = pkbf(e20, e21); H.w = pkbf(e30, e31);
        L.x = pkbf_res(e00, e01, H.x); L.y = pkbf_res(e10, e11, H.y);
        L.z = pkbf_res(e20, e21, H.z); L.w = pkbf_res(e30, e31, H.w);
        const size_t fi = (((size_t)n * 64 + tt) * 16 + kt) * 32 + cl;
        g_Wfh[fi] = H; g_Wfl[fi] = L;
    }
}

// ---------------------------------------------------------------------------
// Kernel 3: O = W @ V + wc @ proj_w via bf16-split mma.sync, no smem.
// Grid (3, 8, 16), block 512 (16 warps, 4x4). Warp tile 32(t) x 32(m).
// ---------------------------------------------------------------------------
__global__ __launch_bounds__(512) void out_gemm_kernel(
    const float* __restrict__ proj_w,  // [2,M]
    float* __restrict__ O)             // [N,T,M]
{
    const int n  = blockIdx.z;
    const int tid = threadIdx.x;
    const int l   = tid & 31;
    const int wi  = tid >> 5;
    const int wm  = wi >> 2, wn = wi & 3;

    const int tt0 = blockIdx.y * 8 + wm * 2;       // ttile base (16-row units)
    const int mt0 = blockIdx.x * 16 + wn * 4;      // mtile base (8-col units)

    const uint4* WH = g_Wfh; const uint4* WL = g_Wfl;
    const uint2* VH = g_Vfh; const uint2* VL = g_Vfl;

    float D[2][4][4];
#pragma unroll
    for (int i = 0; i < 2; i++)
#pragma unroll
        for (int j = 0; j < 4; j++)
#pragma unroll
            for (int q = 0; q < 4; q++) D[i][j][q] = 0.0f;

    uint4 Ah[2][2], Al[2][2];
    uint2 Bh[2][4], Bl[2][4];

#define LOADK(KT, B) do {                                                     \
        const size_t a0i = (((size_t)n * 64 + tt0) * 16 + (KT)) * 32 + l;     \
        const size_t a1i = a0i + 16 * 32;                                     \
        Ah[B][0] = WH[a0i]; Ah[B][1] = WH[a1i];                               \
        Al[B][0] = WL[a0i]; Al[B][1] = WL[a1i];                               \
        const size_t bbi = (((size_t)n * 16 + (KT)) * 48 + mt0) * 32 + l;     \
        _Pragma("unroll")                                                     \
        for (int j = 0; j < 4; j++) {                                         \
            Bh[B][j] = VH[bbi + (size_t)j * 32];                              \
            Bl[B][j] = VL[bbi + (size_t)j * 32];                              \
        }                                                                     \
    } while (0)

    LOADK(0, 0);
#pragma unroll
    for (int kt = 0; kt < 16; kt++) {
        const int cb = kt & 1;
        if (kt < 15) LOADK(kt + 1, cb ^ 1);
#pragma unroll
        for (int i = 0; i < 2; i++)
#pragma unroll
            for (int j = 0; j < 4; j++) {
                mma_bf16(D[i][j], Ah[cb][i], Bh[cb][j]);
                mma_bf16(D[i][j], Ah[cb][i], Bl[cb][j]);
                mma_bf16(D[i][j], Al[cb][i], Bh[cb][j]);
            }
    }
#undef LOADK

    // epilogue
    const int g2 = l >> 2, tg = l & 3;
    float2 pj0[4], pj1[4];
#pragma unroll
    for (int j = 0; j < 4; j++) {
        const int m = (mt0 + j) * 8 + 2 * tg;
        pj0[j] = *reinterpret_cast<const float2*>(&proj_w[m]);
        pj1[j] = *reinterpret_cast<const float2*>(&proj_w[M_ + m]);
    }
#pragma unroll
    for (int i = 0; i < 2; i++) {
        const int r0 = (tt0 + i) * 16 + g2;
        const int r1 = r0 + 8;
        float2 wcA = make_float2(0.f, 0.f), wcB = wcA;
        if (r0 < T_) wcA = *reinterpret_cast<const float2*>(&g_wc[((size_t)n * 1024 + r0) * 2]);
        if (r1 < T_) wcB = *reinterpret_cast<const float2*>(&g_wc[((size_t)n * 1024 + r1) * 2]);
#pragma unroll
        for (int j = 0; j < 4; j++) {
            const int m = (mt0 + j) * 8 + 2 * tg;
            if (r0 < T_) {
                float2 o;
                o.x = D[i][j][0] + wcA.x * pj0[j].x + wcA.y * pj1[j].x;
                o.y = D[i][j][1] + wcA.x * pj0[j].y + wcA.y * pj1[j].y;
                *reinterpret_cast<float2*>(&O[((size_t)n * T_ + r0) * M_ + m]) = o;
            }
            if (r1 < T_) {
                float2 o;
                o.x = D[i][j][2] + wcB.x * pj0[j].x + wcB.y * pj1[j].x;
                o.y = D[i][j][3] + wcB.x * pj0[j].y + wcB.y * pj1[j].y;
                *reinterpret_cast<float2*>(&O[((size_t)n * T_ + r1) * M_ + m]) = o;
            }
        }
    }
}

// ---------------------------------------------------------------------------
extern "C" void kernel_launch(void* const* d_in, const int* in_sizes, int n_in,
                              void* d_out, int out_size)
{
    const float* V        = (const float*)d_in[0];
    const float* dur      = (const float*)d_in[1];
    const float* conv_w   = (const float*)d_in[2];
    const float* conv_b   = (const float*)d_in[3];
    const float* bn_gamma = (const float*)d_in[4];
    const float* bn_beta  = (const float*)d_in[5];
    const float* bn_mean  = (const float*)d_in[6];
    const float* bn_var   = (const float*)d_in[7];
    const float* w1       = (const float*)d_in[8];
    const float* b1       = (const float*)d_in[9];
    const float* w2       = (const float*)d_in[10];
    const float* b2       = (const float*)d_in[11];
    const float* w3       = (const float*)d_in[12];
    const float* b3       = (const float*)d_in[13];
    const float* aw1      = (const float*)d_in[14];
    const float* ab1      = (const float*)d_in[15];
    const float* aw2      = (const float*)d_in[16];
    const float* ab2      = (const float*)d_in[17];
    const float* proj_w   = (const float*)d_in[18];
    float* O = (float*)d_out;

    scan_kernel<<<N_, K_>>>(dur);
    vconv_kernel<<<dim3(16, N_), 256>>>(V);
    conv_fold_kernel<<<(N_ * K_) / 8, 256>>>(V, conv_w, conv_b, bn_gamma, bn_beta,
                                             bn_mean, bn_var, w1, b1, aw1, ab1);
    score_kernel<<<dim3(64, N_), 256>>>(w1, w2, b2, w3, b3, aw1, aw2, ab2);
    out_gemm_kernel<<<dim3(3, 8, N_), 512>>>(proj_w, O);
}

// round 13
// speedup vs baseline: 2.1419x; 1.0932x over previous
#include <cuda_runtime.h>
#include <cuda_bf16.h>
#include <cstddef>
#include <cstdint>

#define N_  16
#define K_  256
#define T_  1000
#define M_  384

typedef unsigned long long u64;

// ---------------- scratch (device globals; no allocations) ----------------
__device__ float g_SE[N_ * K_ * 2];          // S, E per (n,k)
__device__ float g_g [N_ * K_ * 16];         // folded layer-1 bias per (n,k)
__device__ float g_ga[N_ * K_ * 2];          // folded aux layer-1 bias
__device__ float g_wc[N_ * 1024 * 2];        // sum_k W*C (before proj)
// W in m16n8k16 A-fragment layout: [n][ttile(64)][ktile(16)][lane(32)] uint4
__device__ uint4 g_Wfh[(size_t)N_ * 64 * 16 * 32];
__device__ uint4 g_Wfl[(size_t)N_ * 64 * 16 * 32];
// V in B-fragment layout: [n][ktile(16)][mtile(48)][lane(32)] uint2
__device__ uint2 g_Vfh[(size_t)N_ * 16 * 48 * 32];
__device__ uint2 g_Vfl[(size_t)N_ * 16 * 48 * 32];

// ---------------- helpers ---------------
__device__ __forceinline__ u64 pk2(float lo, float hi) {
    u64 d; asm("mov.b64 %0, {%1, %2};" : "=l"(d) : "f"(lo), "f"(hi)); return d;
}
__device__ __forceinline__ u64 pkd(float x) {
    u64 d; asm("mov.b64 %0, {%1, %1};" : "=l"(d) : "f"(x)); return d;
}
__device__ __forceinline__ void upk(u64 v, float& lo, float& hi) {
    asm("mov.b64 {%0, %1}, %2;" : "=f"(lo), "=f"(hi) : "l"(v));
}
__device__ __forceinline__ u64 ffma2(u64 a, u64 b, u64 c) {
    u64 d; asm("fma.rn.f32x2 %0, %1, %2, %3;" : "=l"(d) : "l"(a), "l"(b), "l"(c));
    return d;
}
__device__ __forceinline__ float siluf(float x) {
    float th; const float hx = 0.5f * x;
    asm("tanh.approx.f32 %0, %1;" : "=f"(th) : "f"(hx));
    return fmaf(hx, th, hx);
}
__device__ __forceinline__ float ex2f(float x) {
    float r; asm("ex2.approx.f32 %0, %1;" : "=f"(r) : "f"(x)); return r;
}
// pack (even, odd) -> bf16x2 with even in low 16 bits
__device__ __forceinline__ uint32_t pkbf(float even, float odd) {
    uint32_t r; asm("cvt.rn.bf16x2.f32 %0, %1, %2;" : "=r"(r) : "f"(odd), "f"(even));
    return r;
}
__device__ __forceinline__ uint32_t pkbf_res(float even, float odd, uint32_t hp) {
    const float eh = __uint_as_float(hp << 16);
    const float oh = __uint_as_float(hp & 0xFFFF0000u);
    return pkbf(even - eh, odd - oh);
}
__device__ __forceinline__ void mma_bf16(float d[4], const uint4& a, const uint2& b) {
    asm("mma.sync.aligned.m16n8k16.row.col.f32.bf16.bf16.f32 "
        "{%0,%1,%2,%3},{%4,%5,%6,%7},{%8,%9},{%0,%1,%2,%3};"
        : "+f"(d[0]), "+f"(d[1]), "+f"(d[2]), "+f"(d[3])
        : "r"(a.x), "r"(a.y), "r"(a.z), "r"(a.w), "r"(b.x), "r"(b.y));
}

// ---------------------------------------------------------------------------
// Kernel 0: durations + scan -> S,E.
// ---------------------------------------------------------------------------
__global__ void scan_kernel(const float* __restrict__ dur_out)
{
    __shared__ float wsum[8];
    const int n = blockIdx.x, k = threadIdx.x;
    const int lane = k & 31, warp = k >> 5;

    const float d = fmaxf(__expf(dur_out[n * K_ + k]) - 1.0f, 0.0f);
    float x = d;
#pragma unroll
    for (int off = 1; off < 32; off <<= 1) {
        float y = __shfl_up_sync(0xFFFFFFFFu, x, off);
        if (lane >= off) x += y;
    }
    if (lane == 31) wsum[warp] = x;
    __syncthreads();
    float off = 0.0f;
#pragma unroll
    for (int w = 0; w < 8; w++) off += (w < warp) ? wsum[w] : 0.0f;
    const float Ev = x + off, Sv = Ev - d;
    g_SE[(n * K_ + k) * 2 + 0] = Sv;
    g_SE[(n * K_ + k) * 2 + 1] = Ev;
}

// ---------------------------------------------------------------------------
// Kernel 1: Conv1D(3,same)+BN+silu, fold into g/ga. One warp per (n,k).
// ---------------------------------------------------------------------------
__global__ __launch_bounds__(256) void conv_fold_kernel(
    const float* __restrict__ V,
    const float* __restrict__ conv_w,
    const float* __restrict__ conv_b,
    const float* __restrict__ bn_gamma, const float* __restrict__ bn_beta,
    const float* __restrict__ bn_mean,  const float* __restrict__ bn_var,
    const float* __restrict__ w1,
    const float* __restrict__ b1,
    const float* __restrict__ aw1,
    const float* __restrict__ ab1)
{
    const int tid  = threadIdx.x;
    const int lane = tid & 31;
    const int widx = blockIdx.x * 8 + (tid >> 5);
    const int n = widx >> 8, k = widx & 255;

    u64 acc2[4] = {0ull, 0ull, 0ull, 0ull};
#pragma unroll
    for (int tap = 0; tap < 3; tap++) {
        const int kk = k - 1 + tap;
        if (kk < 0 || kk >= K_) continue;
        const float* vrow = V + ((size_t)n * K_ + kk) * M_;
#pragma unroll
        for (int i = 0; i < 3; i++) {
            const int c0 = i * 128 + lane * 4;
            const float4 v = *reinterpret_cast<const float4*>(vrow + c0);
            const float vv[4] = { v.x, v.y, v.z, v.w };
#pragma unroll
            for (int cc = 0; cc < 4; cc++) {
                const u64 vd = pkd(vv[cc]);
                const float4* wp = reinterpret_cast<const float4*>(
                    conv_w + ((size_t)tap * M_ + c0 + cc) * 8);
                const float4 wa = wp[0], wb = wp[1];
                acc2[0] = ffma2(vd, pk2(wa.x, wa.y), acc2[0]);
                acc2[1] = ffma2(vd, pk2(wa.z, wa.w), acc2[1]);
                acc2[2] = ffma2(vd, pk2(wb.x, wb.y), acc2[2]);
                acc2[3] = ffma2(vd, pk2(wb.z, wb.w), acc2[3]);
            }
        }
    }
    float acc[8];
#pragma unroll
    for (int j = 0; j < 4; j++) upk(acc2[j], acc[2 * j], acc[2 * j + 1]);
#pragma unroll
    for (int s = 16; s > 0; s >>= 1)
#pragma unroll
        for (int o = 0; o < 8; o++)
            acc[o] += __shfl_xor_sync(0xFFFFFFFFu, acc[o], s);

    float cv[8];
#pragma unroll
    for (int o = 0; o < 8; o++) {
        float y = (acc[o] + conv_b[o] - bn_mean[o]) * rsqrtf(bn_var[o] + 1e-3f)
                  * bn_gamma[o] + bn_beta[o];
        cv[o] = siluf(y);
    }
    const float Sv = g_SE[(n * K_ + k) * 2 + 0];
    const float Ev = g_SE[(n * K_ + k) * 2 + 1];
    if (lane < 16) {
        const int j = lane;
        float gj = b1[j] - Sv * w1[j] + Ev * w1[16 + j];
#pragma unroll
        for (int c = 0; c < 8; c++) gj = fmaf(cv[c], w1[(2 + c) * 16 + j], gj);
        g_g[((size_t)n * K_ + k) * 16 + j] = gj;
    } else if (lane < 18) {
        const int p = lane - 16;
        float gp = ab1[p] - Sv * aw1[p] + Ev * aw1[2 + p];
#pragma unroll
        for (int c = 0; c < 8; c++) gp = fmaf(cv[c], aw1[(2 + c) * 2 + p], gp);
        g_ga[((size_t)n * K_ + k) * 2 + p] = gp;
    }
}

// ---------------------------------------------------------------------------
// Kernel V: convert V into bf16 hi/lo B-fragment layout.
// Grid (16 ktile, 16 n), block 256.
// ---------------------------------------------------------------------------
__global__ __launch_bounds__(256) void vconv_kernel(const float* __restrict__ V)
{
    __shared__ float sV[16][388];
    const int kt = blockIdx.x, n = blockIdx.y;
    const int tid = threadIdx.x;

    const float* src = V + ((size_t)n * K_ + kt * 16) * M_;
#pragma unroll
    for (int it = 0; it < 6; it++) {
        const int idx = it * 256 + tid;
        const int row = idx / 96, c4 = idx % 96;
        const float4 v = reinterpret_cast<const float4*>(src + (size_t)row * M_)[c4];
        *reinterpret_cast<float4*>(&sV[row][c4 * 4]) = v;
    }
    __syncthreads();

#pragma unroll
    for (int it = 0; it < 6; it++) {
        const int s = it * 256 + tid;
        const int mt = s >> 5, cl = s & 31;
        const int g2 = cl >> 2, tg = cl & 3;
        const int m = mt * 8 + g2, k0 = 2 * tg;
        const float v00 = sV[k0][m],     v01 = sV[k0 + 1][m];
        const float v10 = sV[k0 + 8][m], v11 = sV[k0 + 9][m];
        uint2 H, L;
        H.x = pkbf(v00, v01); H.y = pkbf(v10, v11);
        L.x = pkbf_res(v00, v01, H.x); L.y = pkbf_res(v10, v11, H.y);
        const size_t fi = (((size_t)n * 16 + kt) * 48 + mt) * 32 + cl;
        g_Vfh[fi] = H; g_Vfl[fi] = L;
    }
}

// ---------------------------------------------------------------------------
// Kernel 2: score MLP + softmax + aux. Thread-per-k, 16-t tile per block,
// processed as 4 quads of 4 t: h2[4][8] in regs, each w2 row loaded ONCE
// per quad as 4x LDS.128 and reused for 4 t's (8x fewer LDS instructions).
// g reloaded per quad (L1-hot) to keep regs under the (256,2) cap.
// Grid (64 ttile, 16 n), block 256. Writes W as bf16 hi/lo A-fragments + g_wc.
// ---------------------------------------------------------------------------
__global__ __launch_bounds__(256, 2) void score_kernel(
    const float* __restrict__ w1,
    const float* __restrict__ w2,
    const float* __restrict__ b2,
    const float* __restrict__ w3,
    const float* __restrict__ b3,
    const float* __restrict__ aw1,
    const float* __restrict__ aw2,
    const float* __restrict__ ab2)
{
    __shared__ __align__(16) u64 s_w2[16][8];
    __shared__ float s_d1[16], s_b2[16], s_w3[16];
    __shared__ float sW[16][257];
    __shared__ float smax[16][8];
    __shared__ float spart[16][8][3];
    __shared__ float sinv[16];

    const int k    = threadIdx.x;      // 0..255
    const int lane = k & 31, warp = k >> 5;
    const int tt   = blockIdx.x;       // ttile 0..63
    const int n    = blockIdx.y;
    const float tb = (float)(tt * 16 + 1);

    if (k < 128) {
        const int i = k & 15, j2 = k >> 4;
        s_w2[i][j2] = pk2(w2[(2 * j2) * 16 + i], w2[(2 * j2 + 1) * 16 + i]);
    }
    if (k < 16) { s_d1[k] = w1[k] - w1[16 + k]; s_b2[k] = b2[k]; s_w3[k] = w3[k]; }
    __syncthreads();

    const float2 gaq = *reinterpret_cast<const float2*>(g_ga + ((size_t)n * K_ + k) * 2);
    const float b3v = b3[0];
    const float da0 = aw1[0] - aw1[2], da1 = aw1[1] - aw1[3];
    const float aw20 = aw2[0], aw21 = aw2[1], aw22 = aw2[2], aw23 = aw2[3];
    const float ab20 = ab2[0], ab21 = ab2[1];

    // ---- phase 1: raw scores -> shared; warp-max partials; 4-t quads ----
#pragma unroll 1
    for (int tq = 0; tq < 4; tq++) {
        // reload folded biases (L1-hot after first quad)
        u64 h2[4][8];
        {
            float g[16];
            const float4* gp = reinterpret_cast<const float4*>(
                g_g + ((size_t)n * K_ + k) * 16);
#pragma unroll
            for (int q4 = 0; q4 < 4; q4++) {
                const float4 v = gp[q4];
                g[4 * q4] = v.x; g[4 * q4 + 1] = v.y;
                g[4 * q4 + 2] = v.z; g[4 * q4 + 3] = v.w;
            }
#pragma unroll
            for (int q = 0; q < 4; q++) {
                const float t = tb + (float)(tq * 4 + q);
#pragma unroll
                for (int j2 = 0; j2 < 8; j2++) {
                    const float a = siluf(fmaf(t, s_d1[2 * j2],     g[2 * j2]));
                    const float b = siluf(fmaf(t, s_d1[2 * j2 + 1], g[2 * j2 + 1]));
                    h2[q][j2] = pk2(a, b);
                }
            }
        }

        float sc[4] = {0.0f, 0.0f, 0.0f, 0.0f};
#pragma unroll 1
        for (int i = 0; i < 16; i++) {
            // load w2 row i once (4 x LDS.128), reuse for 4 t's
            uint4 w4[4];
#pragma unroll
            for (int x = 0; x < 4; x++)
                w4[x] = reinterpret_cast<const uint4*>(&s_w2[i][0])[x];
            const u64* wr = reinterpret_cast<const u64*>(w4);
            const float b2i = s_b2[i], w3i = s_w3[i];
#pragma unroll
            for (int q = 0; q < 4; q++) {
                u64 acc = pk2(b2i, 0.0f);
#pragma unroll
                for (int j2 = 0; j2 < 8; j2++) acc = ffma2(h2[q][j2], wr[j2], acc);
                float lo, hi; upk(acc, lo, hi);
                sc[q] = fmaf(siluf(lo + hi), w3i, sc[q]);
            }
        }

#pragma unroll
        for (int q = 0; q < 4; q++) {
            const int tloc = tq * 4 + q;
            const float scv = b3v + sc[q];
            sW[tloc][k] = scv;
            float m = scv;
#pragma unroll
            for (int s = 16; s > 0; s >>= 1)
                m = fmaxf(m, __shfl_xor_sync(0xFFFFFFFFu, m, s));
            if (lane == 0) smax[tloc][warp] = m;
        }
    }
    __syncthreads();

    // ---- phase 2: exp + aux recompute + warp-sum partials ----
    const float L2E = 1.4426950408889634f;
#pragma unroll 2
    for (int tloc = 0; tloc < 16; tloc++) {
        const float t = tb + (float)tloc;
        float mx = smax[tloc][0];
#pragma unroll
        for (int w = 1; w < 8; w++) mx = fmaxf(mx, smax[tloc][w]);
        const float ev = ex2f((sW[tloc][k] - mx) * L2E);

        const float a0 = siluf(fmaf(t, da0, gaq.x));
        const float a1 = siluf(fmaf(t, da1, gaq.y));
        const float c20 = siluf(ab20 + a0 * aw20 + a1 * aw22);
        const float c21 = siluf(ab21 + a0 * aw21 + a1 * aw23);

        float s0 = ev, s1 = ev * c20, s2 = ev * c21;
#pragma unroll
        for (int s = 16; s > 0; s >>= 1) {
            s0 += __shfl_xor_sync(0xFFFFFFFFu, s0, s);
            s1 += __shfl_xor_sync(0xFFFFFFFFu, s1, s);
            s2 += __shfl_xor_sync(0xFFFFFFFFu, s2, s);
        }
        if (lane == 0) {
            spart[tloc][warp][0] = s0;
            spart[tloc][warp][1] = s1;
            spart[tloc][warp][2] = s2;
        }
        sW[tloc][k] = ev;
    }
    __syncthreads();

    // ---- totals: one thread per t ----
    if (k < 16) {
        float t0s = 0.0f, t1s = 0.0f, t2s = 0.0f;
#pragma unroll
        for (int w = 0; w < 8; w++) {
            t0s += spart[k][w][0]; t1s += spart[k][w][1]; t2s += spart[k][w][2];
        }
        const float inv = __fdividef(1.0f, t0s);
        sinv[k] = inv;
        *reinterpret_cast<float2*>(&g_wc[((size_t)n * 1024 + tt * 16 + k) * 2]) =
            make_float2(t1s * inv, t2s * inv);
    }
    __syncthreads();

    // ---- phase 3: normalize in shared ----
#pragma unroll 2
    for (int tloc = 0; tloc < 16; tloc++)
        sW[tloc][k] *= sinv[tloc];
    __syncthreads();

    // ---- fragment conversion (bf16 hi/lo, coalesced STG.128) ----
#pragma unroll 1
    for (int it2 = 0; it2 < 2; it2++) {
        const int idx = it2 * 256 + k;
        const int kt = idx >> 5, cl = idx & 31;
        const int g2 = cl >> 2, tg = cl & 3;
        const int c0 = kt * 16 + 2 * tg;
        const float e00 = sW[g2][c0],         e01 = sW[g2][c0 + 1];
        const float e10 = sW[g2 + 8][c0],     e11 = sW[g2 + 8][c0 + 1];
        const float e20 = sW[g2][c0 + 8],     e21 = sW[g2][c0 + 9];
        const float e30 = sW[g2 + 8][c0 + 8], e31 = sW[g2 + 8][c0 + 9];
        uint4 H, L;
        H.x = pkbf(e00, e01); H.y = pkbf(e10, e11);
        H.z = pkbf(e20, e21); H.w = pkbf(e30, e31);
        L.x = pkbf_res(e00, e01, H.x); L.y = pkbf_res(e10, e11, H.y);
        L.z = pkbf_res(e20, e21, H.z); L.w = pkbf_res(e30, e31, H.w);
        const size_t fi = (((size_t)n * 64 + tt) * 16 + kt) * 32 + cl;
        g_Wfh[fi] = H; g_Wfl[fi] = L;
    }
}

// ---------------------------------------------------------------------------
// Kernel 3: O = W @ V + wc @ proj_w via bf16-split mma.sync, no smem.
// Grid (3, 8, 16), block 512 (16 warps, 4x4). Warp tile 32(t) x 32(m).
// ---------------------------------------------------------------------------
__global__ __launch_bounds__(512) void out_gemm_kernel(
    const float* __restrict__ proj_w,  // [2,M]
    float* __restrict__ O)             // [N,T,M]
{
    const int n  = blockIdx.z;
    const int tid = threadIdx.x;
    const int l   = tid & 31;
    const int wi  = tid >> 5;
    const int wm  = wi >> 2, wn = wi & 3;

    const int tt0 = blockIdx.y * 8 + wm * 2;       // ttile base (16-row units)
    const int mt0 = blockIdx.x * 16 + wn * 4;      // mtile base (8-col units)

    const uint4* WH = g_Wfh; const uint4* WL = g_Wfl;
    const uint2* VH = g_Vfh; const uint2* VL = g_Vfl;

    float D[2][4][4];
#pragma unroll
    for (int i = 0; i < 2; i++)
#pragma unroll
        for (int j = 0; j < 4; j++)
#pragma unroll
            for (int q = 0; q < 4; q++) D[i][j][q] = 0.0f;

    uint4 Ah[2][2], Al[2][2];
    uint2 Bh[2][4], Bl[2][4];

#define LOADK(KT, B) do {                                                     \
        const size_t a0i = (((size_t)n * 64 + tt0) * 16 + (KT)) * 32 + l;     \
        const size_t a1i = a0i + 16 * 32;                                     \
        Ah[B][0] = WH[a0i]; Ah[B][1] = WH[a1i];                               \
        Al[B][0] = WL[a0i]; Al[B][1] = WL[a1i];                               \
        const size_t bbi = (((size_t)n * 16 + (KT)) * 48 + mt0) * 32 + l;     \
        _Pragma("unroll")                                                     \
        for (int j = 0; j < 4; j++) {                                         \
            Bh[B][j] = VH[bbi + (size_t)j * 32];                              \
            Bl[B][j] = VL[bbi + (size_t)j * 32];                              \
        }                                                                     \
    } while (0)

    LOADK(0, 0);
#pragma unroll
    for (int kt = 0; kt < 16; kt++) {
        const int cb = kt & 1;
        if (kt < 15) LOADK(kt + 1, cb ^ 1);
#pragma unroll
        for (int i = 0; i < 2; i++)
#pragma unroll
            for (int j = 0; j < 4; j++) {
                mma_bf16(D[i][j], Ah[cb][i], Bh[cb][j]);
                mma_bf16(D[i][j], Ah[cb][i], Bl[cb][j]);
                mma_bf16(D[i][j], Al[cb][i], Bh[cb][j]);
            }
    }
#undef LOADK

    // epilogue
    const int g2 = l >> 2, tg = l & 3;
    float2 pj0[4], pj1[4];
#pragma unroll
    for (int j = 0; j < 4; j++) {
        const int m = (mt0 + j) * 8 + 2 * tg;
        pj0[j] = *reinterpret_cast<const float2*>(&proj_w[m]);
        pj1[j] = *reinterpret_cast<const float2*>(&proj_w[M_ + m]);
    }
#pragma unroll
    for (int i = 0; i < 2; i++) {
        const int r0 = (tt0 + i) * 16 + g2;
        const int r1 = r0 + 8;
        float2 wcA = make_float2(0.f, 0.f), wcB = wcA;
        if (r0 < T_) wcA = *reinterpret_cast<const float2*>(&g_wc[((size_t)n * 1024 + r0) * 2]);
        if (r1 < T_) wcB = *reinterpret_cast<const float2*>(&g_wc[((size_t)n * 1024 + r1) * 2]);
#pragma unroll
        for (int j = 0; j < 4; j++) {
            const int m = (mt0 + j) * 8 + 2 * tg;
            if (r0 < T_) {
                float2 o;
                o.x = D[i][j][0] + wcA.x * pj0[j].x + wcA.y * pj1[j].x;
                o.y = D[i][j][1] + wcA.x * pj0[j].y + wcA.y * pj1[j].y;
                *reinterpret_cast<float2*>(&O[((size_t)n * T_ + r0) * M_ + m]) = o;
            }
            if (r1 < T_) {
                float2 o;
                o.x = D[i][j][2] + wcB.x * pj0[j].x + wcB.y * pj1[j].x;
                o.y = D[i][j][3] + wcB.x * pj0[j].y + wcB.y * pj1[j].y;
                *reinterpret_cast<float2*>(&O[((size_t)n * T_ + r1) * M_ + m]) = o;
            }
        }
    }
}

// ---------------------------------------------------------------------------
extern "C" void kernel_launch(void* const* d_in, const int* in_sizes, int n_in,
                              void* d_out, int out_size)
{
    const float* V        = (const float*)d_in[0];
    const float* dur      = (const float*)d_in[1];
    const float* conv_w   = (const float*)d_in[2];
    const float* conv_b   = (const float*)d_in[3];
    const float* bn_gamma = (const float*)d_in[4];
    const float* bn_beta  = (const float*)d_in[5];
    const float* bn_mean  = (const float*)d_in[6];
    const float* bn_var   = (const float*)d_in[7];
    const float* w1       = (const float*)d_in[8];
    const float* b1       = (const float*)d_in[9];
    const float* w2       = (const float*)d_in[10];
    const float* b2       = (const float*)d_in[11];
    const float* w3       = (const float*)d_in[12];
    const float* b3       = (const float*)d_in[13];
    const float* aw1      = (const float*)d_in[14];
    const float* ab1      = (const float*)d_in[15];
    const float* aw2      = (const float*)d_in[16];
    const float* ab2      = (const float*)d_in[17];
    const float* proj_w   = (const float*)d_in[18];
    float* O = (float*)d_out;

    scan_kernel<<<N_, K_>>>(dur);
    vconv_kernel<<<dim3(16, N_), 256>>>(V);
    conv_fold_kernel<<<(N_ * K_) / 8, 256>>>(V, conv_w, conv_b, bn_gamma, bn_beta,
                                             bn_mean, bn_var, w1, b1, aw1, ab1);
    score_kernel<<<dim3(64, N_), 256>>>(w1, w2, b2, w3, b3, aw1, aw2, ab2);
    out_gemm_kernel<<<dim3(3, 8, N_), 512>>>(proj_w, O);
}